// round 11
// baseline (speedup 1.0000x reference)
#include <cuda_runtime.h>

#define M_ROWS 12288
#define N_COLS 12288
#define D_DIM  128
#define INV_T  (1.0f/0.07f)
#define IDXCAP 128
#define NCACHE 32
#define SCAN_TB 256
#define SCAN_IT ((N_COLS/4)/SCAN_TB)   // 12 int4 loads per thread

// static scratch (allocation-free)
__device__ float g_xa[(size_t)M_ROWS * D_DIM];
__device__ int   g_cnt[M_ROWS];
__device__ int   g_idx[(size_t)M_ROWS * IDXCAP];

// ---------------------------------------------------------------------------
// Kernel S+A fused: adjacency stream + per-row matvec in the idle issue slots.
// adj loads use __ldcs (evict-first): the 604MB single-use stream must not
// evict g_xa/g_idx (12MB) that attn needs right after -- R10 showed attn
// re-reading ~14MB from DRAM (+10us) because the stream flushed L2.
// ---------------------------------------------------------------------------
__global__ void __launch_bounds__(SCAN_TB) scan_xw_kernel(const int4*   __restrict__ adj4,
                                                          const float4* __restrict__ xanchor4,
                                                          const float4* __restrict__ W4) {
    __shared__ int    s_cnt;
    __shared__ float4 s_x[D_DIM / 4];        // anchor row (512B)
    __shared__ float4 s_part[8][D_DIM / 4];  // matvec partials (4KB)

    const int m   = blockIdx.x;
    const int tid = threadIdx.x;

    if (tid == 0) s_cnt = 0;
    if (tid < 32) s_x[tid] = xanchor4[(size_t)m * 32 + tid];

    // ---- adj row: front-batched STREAMING loads (evict-first in L2) ----
    const int4* row = adj4 + (size_t)m * (N_COLS / 4);
    int4 v[SCAN_IT];
    #pragma unroll
    for (int it = 0; it < SCAN_IT; it++)
        v[it] = __ldcs(row + it * SCAN_TB + tid);

    __syncthreads();   // s_x + s_cnt visible; adj loads still in flight

    // ---- matvec partials while adj loads are in flight ----
    {
        const int e4 = tid & 31;   // float4 output column group (warp-coalesced)
        const int dh = tid >> 5;   // 8 chunks of 16 d-values (warp-uniform)
        float4 acc = make_float4(0.f, 0.f, 0.f, 0.f);
        #pragma unroll
        for (int i = 0; i < 16; i++) {
            const int   d  = dh * 16 + i;
            const float xd = reinterpret_cast<const float*>(s_x)[d];  // warp broadcast
            const float4 w = W4[(size_t)d * 32 + e4];                 // L1-hot LDG.128
            acc.x += xd * w.x; acc.y += xd * w.y;
            acc.z += xd * w.z; acc.w += xd * w.w;
        }
        s_part[dh][e4] = acc;
    }

    // ---- consume adj bits (scoreboard waits on the DRAM loads here) ----
    int* rowidx = g_idx + (size_t)m * IDXCAP;
    #pragma unroll
    for (int it = 0; it < SCAN_IT; it++) {
        if (v[it].x | v[it].y | v[it].z | v[it].w) {
            int base = (it * SCAN_TB + tid) * 4;
            if (v[it].x) { int p = atomicAdd(&s_cnt, 1); if (p < IDXCAP) rowidx[p] = base;     }
            if (v[it].y) { int p = atomicAdd(&s_cnt, 1); if (p < IDXCAP) rowidx[p] = base + 1; }
            if (v[it].z) { int p = atomicAdd(&s_cnt, 1); if (p < IDXCAP) rowidx[p] = base + 2; }
            if (v[it].w) { int p = atomicAdd(&s_cnt, 1); if (p < IDXCAP) rowidx[p] = base + 3; }
        }
    }
    __syncthreads();

    if (tid == 0) g_cnt[m] = min(s_cnt, IDXCAP);

    // ---- reduce matvec partials, write xa row ----
    if (tid < 32) {
        float4 r = s_part[0][tid];
        #pragma unroll
        for (int dh = 1; dh < 8; dh++) {
            float4 p = s_part[dh][tid];
            r.x += p.x; r.y += p.y; r.z += p.z; r.w += p.w;
        }
        reinterpret_cast<float4*>(g_xa)[(size_t)m * 32 + tid] = r;
    }
}

// ---------------------------------------------------------------------------
// Kernel C: gather-once smem row cache + fused scores, block softmax,
// aggregation. With .cs scan loads, g_xa/g_idx stay L2-resident.
// ---------------------------------------------------------------------------
__global__ void __launch_bounds__(128) attn_compute(const float* __restrict__ xin,
                                                    float*       __restrict__ out) {
    __shared__ float s_rows[NCACHE][D_DIM];
    __shared__ float s_xa[D_DIM];
    __shared__ int   s_idx[IDXCAP];
    __shared__ float s_val[IDXCAP];
    __shared__ float s_sum;

    const int m    = blockIdx.x;
    const int tid  = threadIdx.x;
    const int wid  = tid >> 5;
    const int lane = tid & 31;

    const int cnt = g_cnt[m];
    s_xa[tid] = g_xa[(size_t)m * D_DIM + tid];
    if (tid < cnt) s_idx[tid] = g_idx[(size_t)m * IDXCAP + tid];
    __syncthreads();

    if (cnt == 0) {
        float acc = 0.f;
        for (int n = 0; n < N_COLS; n++)
            acc += xin[(size_t)n * D_DIM + tid];
        out[(size_t)m * D_DIM + tid] = acc * (1.0f / N_COLS);
        return;
    }

    const int nc = min(cnt, NCACHE);
    const float4 b = reinterpret_cast<const float4*>(s_xa)[lane];

    for (int k = wid; k < nc; k += 4) {
        const float4* r = reinterpret_cast<const float4*>(xin)
                        + (size_t)s_idx[k] * (D_DIM / 4);
        float4 a = r[lane];
        reinterpret_cast<float4*>(&s_rows[k][0])[lane] = a;
        float p = a.x * b.x + a.y * b.y + a.z * b.z + a.w * b.w;
        #pragma unroll
        for (int o = 16; o; o >>= 1) p += __shfl_xor_sync(0xffffffffu, p, o);
        if (lane == 0) s_val[k] = p;
    }
    for (int k = NCACHE + wid; k < cnt; k += 4) {
        const float4* r = reinterpret_cast<const float4*>(xin)
                        + (size_t)s_idx[k] * (D_DIM / 4);
        float4 a = r[lane];
        float p = a.x * b.x + a.y * b.y + a.z * b.z + a.w * b.w;
        #pragma unroll
        for (int o = 16; o; o >>= 1) p += __shfl_xor_sync(0xffffffffu, p, o);
        if (lane == 0) s_val[k] = p;
    }
    __syncthreads();

    if (wid == 0) {
        float mx = -3.0e38f;
        for (int k = lane; k < cnt; k += 32) mx = fmaxf(mx, s_val[k]);
        #pragma unroll
        for (int o = 16; o; o >>= 1) mx = fmaxf(mx, __shfl_xor_sync(0xffffffffu, mx, o));
        float sm = 0.f;
        for (int k = lane; k < cnt; k += 32) {
            float e = __expf((s_val[k] - mx) * INV_T);
            s_val[k] = e;
            sm += e;
        }
        #pragma unroll
        for (int o = 16; o; o >>= 1) sm += __shfl_xor_sync(0xffffffffu, sm, o);
        if (lane == 0) s_sum = sm;
    }
    __syncthreads();

    float acc = 0.f;
    #pragma unroll 4
    for (int k = 0; k < nc; k++)
        acc += s_val[k] * s_rows[k][tid];
    for (int k = nc; k < cnt; k++)
        acc += s_val[k] * xin[(size_t)s_idx[k] * D_DIM + tid];
    out[(size_t)m * D_DIM + tid] = acc / s_sum;
}

// ---------------------------------------------------------------------------
// inputs: 0=xx_anchor [12288,128] f32, 1=input [12288,128] f32,
//         2=adj [12288,12288] i32,    3=weight [128,128] f32
// output: [12288,128] f32
//
// Two serial kernels (stream overlap categorically dead: R3/R5/R8/R9).
// xw fused into scan's idle issue slots; adj loads streamed (.cs) so the
// 604MB single-use stream doesn't evict attn's 12MB working set from L2.
// ---------------------------------------------------------------------------
extern "C" void kernel_launch(void* const* d_in, const int* in_sizes, int n_in,
                              void* d_out, int out_size) {
    const float* xx_anchor = (const float*)d_in[0];
    const float* input     = (const float*)d_in[1];
    const int*   adj       = (const int*)  d_in[2];
    const float* weight    = (const float*)d_in[3];
    float*       out       = (float*)d_out;

    scan_xw_kernel<<<M_ROWS, SCAN_TB>>>((const int4*)adj,
                                        (const float4*)xx_anchor,
                                        (const float4*)weight);
    attn_compute<<<M_ROWS, 128>>>(input, out);
}

// round 12
// speedup vs baseline: 1.0305x; 1.0305x over previous
#include <cuda_runtime.h>

#define M_ROWS 12288
#define N_COLS 12288
#define D_DIM  128
#define INV_T  (1.0f/0.07f)
#define IDXCAP 128
#define NCACHE 32
#define SCAN_TB 256
#define SCAN_IT ((N_COLS/4)/SCAN_TB)   // 12 int4 loads per thread

// static scratch (allocation-free)
__device__ float g_xa[(size_t)M_ROWS * D_DIM];
__device__ int   g_cnt[M_ROWS];
__device__ int   g_idx[(size_t)M_ROWS * IDXCAP];
__device__ float g_sink;               // dead-store target for warm kernel

// ---------------------------------------------------------------------------
// Kernel S+A fused (R10-proven, 98.2us): adjacency stream + matvec in idle
// issue slots. Plain loads -- .cs cost 7us in R11 and bought nothing.
// ---------------------------------------------------------------------------
__global__ void __launch_bounds__(SCAN_TB) scan_xw_kernel(const int4*   __restrict__ adj4,
                                                          const float4* __restrict__ xanchor4,
                                                          const float4* __restrict__ W4) {
    __shared__ int    s_cnt;
    __shared__ float4 s_x[D_DIM / 4];        // anchor row (512B)
    __shared__ float4 s_part[8][D_DIM / 4];  // matvec partials (4KB)

    const int m   = blockIdx.x;
    const int tid = threadIdx.x;

    if (tid == 0) s_cnt = 0;
    if (tid < 32) s_x[tid] = xanchor4[(size_t)m * 32 + tid];

    // ---- adj row: front-batched DRAM loads (issue before any compute) ----
    const int4* row = adj4 + (size_t)m * (N_COLS / 4);
    int4 v[SCAN_IT];
    #pragma unroll
    for (int it = 0; it < SCAN_IT; it++)
        v[it] = row[it * SCAN_TB + tid];

    __syncthreads();   // s_x + s_cnt visible; adj loads still in flight

    // ---- matvec partials while adj loads are in flight ----
    {
        const int e4 = tid & 31;
        const int dh = tid >> 5;
        float4 acc = make_float4(0.f, 0.f, 0.f, 0.f);
        #pragma unroll
        for (int i = 0; i < 16; i++) {
            const int   d  = dh * 16 + i;
            const float xd = reinterpret_cast<const float*>(s_x)[d];  // warp broadcast
            const float4 w = W4[(size_t)d * 32 + e4];                 // L1-hot LDG.128
            acc.x += xd * w.x; acc.y += xd * w.y;
            acc.z += xd * w.z; acc.w += xd * w.w;
        }
        s_part[dh][e4] = acc;
    }

    // ---- consume adj bits (scoreboard waits on the DRAM loads here) ----
    int* rowidx = g_idx + (size_t)m * IDXCAP;
    #pragma unroll
    for (int it = 0; it < SCAN_IT; it++) {
        if (v[it].x | v[it].y | v[it].z | v[it].w) {
            int base = (it * SCAN_TB + tid) * 4;
            if (v[it].x) { int p = atomicAdd(&s_cnt, 1); if (p < IDXCAP) rowidx[p] = base;     }
            if (v[it].y) { int p = atomicAdd(&s_cnt, 1); if (p < IDXCAP) rowidx[p] = base + 1; }
            if (v[it].z) { int p = atomicAdd(&s_cnt, 1); if (p < IDXCAP) rowidx[p] = base + 2; }
            if (v[it].w) { int p = atomicAdd(&s_cnt, 1); if (p < IDXCAP) rowidx[p] = base + 3; }
        }
    }
    __syncthreads();

    if (tid == 0) g_cnt[m] = min(s_cnt, IDXCAP);

    // ---- reduce matvec partials, write xa row ----
    if (tid < 32) {
        float4 r = s_part[0][tid];
        #pragma unroll
        for (int dh = 1; dh < 8; dh++) {
            float4 p = s_part[dh][tid];
            r.x += p.x; r.y += p.y; r.z += p.z; r.w += p.w;
        }
        reinterpret_cast<float4*>(g_xa)[(size_t)m * 32 + tid] = r;
    }
}

// ---------------------------------------------------------------------------
// Kernel W: re-warm L2 with attn's working set (g_xa + g_idx + g_cnt,
// 12.6MB) -- the 604MB adj stream evicted the early rows. ~2-3us.
// ---------------------------------------------------------------------------
__global__ void __launch_bounds__(256) warm_kernel() {
    const int nthr = 256 * 256;
    const int t    = blockIdx.x * 256 + threadIdx.x;
    float acc = 0.f;

    const float4* xa4 = reinterpret_cast<const float4*>(g_xa);
    const int4*   id4 = reinterpret_cast<const int4*>(g_idx);
    const int     n4  = M_ROWS * (D_DIM / 4);          // 393216 float4/int4 each

    for (int i = t; i < n4; i += nthr) {
        float4 a = xa4[i];
        int4   b = id4[i];
        acc += a.x + a.w + (float)(b.x ^ b.w);
    }
    for (int i = t; i < M_ROWS; i += nthr)
        acc += (float)g_cnt[i];

    if (acc == 1.2345678e-30f) g_sink = acc;  // never taken; defeats DCE
}

// ---------------------------------------------------------------------------
// Kernel C (proven): gather-once smem row cache + fused scores, block
// softmax, aggregation. With warm L2 its startup loads are L2 hits.
// ---------------------------------------------------------------------------
__global__ void __launch_bounds__(128) attn_compute(const float* __restrict__ xin,
                                                    float*       __restrict__ out) {
    __shared__ float s_rows[NCACHE][D_DIM];
    __shared__ float s_xa[D_DIM];
    __shared__ int   s_idx[IDXCAP];
    __shared__ float s_val[IDXCAP];
    __shared__ float s_sum;

    const int m    = blockIdx.x;
    const int tid  = threadIdx.x;
    const int wid  = tid >> 5;
    const int lane = tid & 31;

    const int cnt = g_cnt[m];
    s_xa[tid] = g_xa[(size_t)m * D_DIM + tid];
    if (tid < cnt) s_idx[tid] = g_idx[(size_t)m * IDXCAP + tid];
    __syncthreads();

    if (cnt == 0) {
        float acc = 0.f;
        for (int n = 0; n < N_COLS; n++)
            acc += xin[(size_t)n * D_DIM + tid];
        out[(size_t)m * D_DIM + tid] = acc * (1.0f / N_COLS);
        return;
    }

    const int nc = min(cnt, NCACHE);
    const float4 b = reinterpret_cast<const float4*>(s_xa)[lane];

    for (int k = wid; k < nc; k += 4) {
        const float4* r = reinterpret_cast<const float4*>(xin)
                        + (size_t)s_idx[k] * (D_DIM / 4);
        float4 a = r[lane];
        reinterpret_cast<float4*>(&s_rows[k][0])[lane] = a;
        float p = a.x * b.x + a.y * b.y + a.z * b.z + a.w * b.w;
        #pragma unroll
        for (int o = 16; o; o >>= 1) p += __shfl_xor_sync(0xffffffffu, p, o);
        if (lane == 0) s_val[k] = p;
    }
    for (int k = NCACHE + wid; k < cnt; k += 4) {
        const float4* r = reinterpret_cast<const float4*>(xin)
                        + (size_t)s_idx[k] * (D_DIM / 4);
        float4 a = r[lane];
        float p = a.x * b.x + a.y * b.y + a.z * b.z + a.w * b.w;
        #pragma unroll
        for (int o = 16; o; o >>= 1) p += __shfl_xor_sync(0xffffffffu, p, o);
        if (lane == 0) s_val[k] = p;
    }
    __syncthreads();

    if (wid == 0) {
        float mx = -3.0e38f;
        for (int k = lane; k < cnt; k += 32) mx = fmaxf(mx, s_val[k]);
        #pragma unroll
        for (int o = 16; o; o >>= 1) mx = fmaxf(mx, __shfl_xor_sync(0xffffffffu, mx, o));
        float sm = 0.f;
        for (int k = lane; k < cnt; k += 32) {
            float e = __expf((s_val[k] - mx) * INV_T);
            s_val[k] = e;
            sm += e;
        }
        #pragma unroll
        for (int o = 16; o; o >>= 1) sm += __shfl_xor_sync(0xffffffffu, sm, o);
        if (lane == 0) s_sum = sm;
    }
    __syncthreads();

    float acc = 0.f;
    #pragma unroll 4
    for (int k = 0; k < nc; k++)
        acc += s_val[k] * s_rows[k][tid];
    for (int k = nc; k < cnt; k++)
        acc += s_val[k] * xin[(size_t)s_idx[k] * D_DIM + tid];
    out[(size_t)m * D_DIM + tid] = acc / s_sum;
}

// ---------------------------------------------------------------------------
// inputs: 0=xx_anchor [12288,128] f32, 1=input [12288,128] f32,
//         2=adj [12288,12288] i32,    3=weight [128,128] f32
// output: [12288,128] f32
//
// Three serial kernels: fused scan+xw (98us), L2 re-warm (~3us), attn.
// Stream overlap categorically dead (R3/R5/R8/R9). The warm kernel directly
// tests the L2-state theory for attn's R8(29us)-vs-R10(38.7us) gap.
// ---------------------------------------------------------------------------
extern "C" void kernel_launch(void* const* d_in, const int* in_sizes, int n_in,
                              void* d_out, int out_size) {
    const float* xx_anchor = (const float*)d_in[0];
    const float* input     = (const float*)d_in[1];
    const int*   adj       = (const int*)  d_in[2];
    const float* weight    = (const float*)d_in[3];
    float*       out       = (float*)d_out;

    scan_xw_kernel<<<M_ROWS, SCAN_TB>>>((const int4*)adj,
                                        (const float4*)xx_anchor,
                                        (const float4*)weight);
    warm_kernel<<<256, 256>>>();
    attn_compute<<<M_ROWS, 128>>>(input, out);
}